// round 16
// baseline (speedup 1.0000x reference)
#include <cuda_runtime.h>
#include <math.h>

#define Bt    16
#define St    128
#define Nn    2048
#define Ee    2032
#define Hh    256
#define DEc   192
#define DRc   64
#define Lc    12
#define NLEVc 21
#define NCTA  144
#define NTH   512

typedef unsigned long long u64;

// ---------------- device scratch (no dynamic allocation allowed) ------------
__device__ float g_ix[Nn * Hh];
__device__ float g_fx[Nn * Hh];
__device__ float g_ox[Nn * Hh];
__device__ float g_ux[Nn * Hh];
__device__ float g_h [Nn * Hh];
__device__ float g_c [Nn * Hh];
__device__ float g_pool[Bt * 8 * Hh];
__device__ int   g_child_start[Nn + 1];
__device__ int   g_child_list [Ee];
__device__ int   g_level_nodes[Nn];
__device__ int   g_done[Nn];
__device__ int   g_nleaf;
__device__ int   g_curL[8 * 32];     // leaf cursor per column-block
__device__ int   g_curI[8 * 32];     // interior cursor per column-block

// ---------------- helpers ----------------------------------------------------
__device__ __forceinline__ u64 dup2(float a) {
    u64 r; asm("mov.b64 %0,{%1,%1};" : "=l"(r) : "f"(a)); return r;
}
__device__ __forceinline__ void fma2(u64& d, u64 a, u64 b) {
    asm("fma.rn.f32x2 %0,%1,%2,%0;" : "+l"(d) : "l"(a), "l"(b));
}
__device__ __forceinline__ float red2(u64 v) {
    float a, b; asm("mov.b64 {%0,%1},%2;" : "=f"(a), "=f"(b) : "l"(v));
    return a + b;
}
__device__ __forceinline__ float lo2(u64 v) {
    float a, b; asm("mov.b64 {%0,%1},%2;" : "=f"(a), "=f"(b) : "l"(v)); return a;
}
__device__ __forceinline__ float hi2(u64 v) {
    float a, b; asm("mov.b64 {%0,%1},%2;" : "=f"(a), "=f"(b) : "l"(v)); return b;
}
__device__ __forceinline__ int ldacq(const int* p) {
    int v; asm volatile("ld.acquire.gpu.global.s32 %0,[%1];" : "=r"(v) : "l"(p) : "memory");
    return v;
}
__device__ __forceinline__ void red_release(int* p) {
    asm volatile("red.release.gpu.global.add.s32 [%0],1;" :: "l"(p) : "memory");
}
__device__ __forceinline__ void waitdone(const int* p) {
    int it = 0;
    while (ldacq(p) != 8) { if (++it > 200) __nanosleep(64); }
}
__device__ __forceinline__ float sigm(float x) { return 1.f / (1.f + __expf(-x)); }

// ---------------- preprocess: flags + child CSR + level lists + cursors -----
__global__ void __launch_bounds__(512) preprocess_kernel(
    const int* __restrict__ child_idx,
    const int* __restrict__ parent_idx,
    const int* __restrict__ node_height)
{
    __shared__ int s_cnt[Nn];
    __shared__ int s_aux[512];
    __shared__ int s_par[Ee];
    __shared__ int s_lvl[NLEVc + 1];
    const int t = threadIdx.x;

    for (int i = t; i < Nn; i += 512) { s_cnt[i] = 0; g_done[i] = 0; }
    for (int e = t; e < Ee; e += 512) s_par[e] = parent_idx[e];
    if (t <= NLEVc) s_lvl[t] = 0;
    __syncthreads();

    for (int e = t; e < Ee; e += 512) atomicAdd(&s_cnt[s_par[e]], 1);
    for (int i = t; i < Nn; i += 512) atomicAdd(&s_lvl[node_height[i]], 1);
    __syncthreads();

    int v[4]; int s = 0;
#pragma unroll
    for (int r = 0; r < 4; r++) { v[r] = s_cnt[t * 4 + r]; s += v[r]; }
    s_aux[t] = s;
    __syncthreads();
    for (int off = 1; off < 512; off <<= 1) {
        int x = (t >= off) ? s_aux[t - off] : 0;
        __syncthreads();
        s_aux[t] += x;
        __syncthreads();
    }
    int run = (t == 0) ? 0 : s_aux[t - 1];
#pragma unroll
    for (int r = 0; r < 4; r++) {
        int c = v[r];
        g_child_start[t * 4 + r] = run;
        s_cnt[t * 4 + r] = run;
        run += c;
    }
    if (t == 511) g_child_start[Nn] = run;
    __syncthreads();

    if (t == 0) {
        int acc = 0;
        for (int l = 0; l < NLEVc; l++) {
            int c = s_lvl[l];
            s_lvl[l] = acc;
            acc += c;
        }
        int nleaf = s_lvl[1];              // level-0 count = #leaves
        g_nleaf = nleaf;
        for (int i = 0; i < 8; i++) { g_curL[i * 32] = 0; g_curI[i * 32] = nleaf; }
    }
    __syncthreads();

    // warp-per-tree child scatter: rank = #earlier same-parent edges in tree
    {
        int w = t >> 5, lane = t & 31;
        if (w < Bt) {
            int e0 = w * (St - 1);
            for (int el = lane; el < St - 1; el += 32) {
                int e = e0 + el;
                int p = s_par[e];
                int rank = 0;
                for (int e2 = e0; e2 < e; ++e2) rank += (s_par[e2] == p) ? 1 : 0;
                g_child_list[s_cnt[p] + rank] = child_idx[e];
            }
        }
    }
    // level-node scatter (intra-level order irrelevant)
    for (int i = t; i < Nn; i += 512) {
        int pos = atomicAdd(&s_lvl[node_height[i]], 1);
        g_level_nodes[pos] = i;
    }
}

// ---------------- fused embed + input GEMMs: x[2048,256] @ W[256,256] (x4) --
__global__ void __launch_bounds__(256) input_gemm_kernel(
    const int* __restrict__ xs, const int* __restrict__ rels,
    const float* __restrict__ embW, const float* __restrict__ relW,
    const float* __restrict__ Wix, const float* __restrict__ Wfx,
    const float* __restrict__ Wox, const float* __restrict__ Wux,
    const float* __restrict__ bix, const float* __restrict__ bfx)
{
    __shared__ __align__(16) float As[16][68];
    __shared__ __align__(16) float Bs[16][68];
    __shared__ int s_xs[64], s_rels[64];
    const int mz = blockIdx.z;
    const float* W  = (mz == 0) ? Wix : (mz == 1) ? Wfx : (mz == 2) ? Wox : Wux;
    const float* bp = (mz == 0) ? bix : (mz == 1) ? bfx : nullptr;
    float* O = (mz == 0) ? g_ix : (mz == 1) ? g_fx : (mz == 2) ? g_ox : g_ux;

    const int t = threadIdx.x;
    const int tx = t & 15, ty = t >> 4;
    const int row0 = blockIdx.y * 64, col0 = blockIdx.x * 64;
    if (t < 64) { s_xs[t] = xs[row0 + t]; s_rels[t] = rels[row0 + t]; }
    __syncthreads();

    u64 acc[4][2] = {};

    for (int kk = 0; kk < 256; kk += 16) {
        {
            int m = t >> 2, kq = (t & 3) * 4;
            int gk = kk + kq;
            float4 a;
            if (gk < DEc) a = *(const float4*)(embW + (size_t)s_xs[m] * DEc + gk);
            else          a = *(const float4*)(relW + (size_t)s_rels[m] * DRc + (gk - DEc));
            As[kq + 0][m] = a.x; As[kq + 1][m] = a.y;
            As[kq + 2][m] = a.z; As[kq + 3][m] = a.w;
            int k = t >> 4, nq = (t & 15) * 4;
            float4 b = *(const float4*)(W + (kk + k) * 256 + col0 + nq);
            *(float4*)&Bs[k][nq] = b;
        }
        __syncthreads();
#pragma unroll
        for (int k = 0; k < 16; k++) {
            float4 a = *(const float4*)&As[k][ty * 4];
            u64 b0 = *(const u64*)&Bs[k][tx * 4];
            u64 b1 = *(const u64*)&Bs[k][tx * 4 + 2];
            u64 d;
            d = dup2(a.x); fma2(acc[0][0], d, b0); fma2(acc[0][1], d, b1);
            d = dup2(a.y); fma2(acc[1][0], d, b0); fma2(acc[1][1], d, b1);
            d = dup2(a.z); fma2(acc[2][0], d, b0); fma2(acc[2][1], d, b1);
            d = dup2(a.w); fma2(acc[3][0], d, b0); fma2(acc[3][1], d, b1);
        }
        __syncthreads();
    }
    int cc0 = col0 + tx * 4;
    float4 bb = make_float4(0.f, 0.f, 0.f, 0.f);
    if (bp) bb = *(const float4*)(bp + cc0);
#pragma unroll
    for (int r = 0; r < 4; r++) {
        int row = row0 + ty * 4 + r;
        float4 o;
        o.x = lo2(acc[r][0]) + bb.x; o.y = hi2(acc[r][0]) + bb.y;
        o.z = lo2(acc[r][1]) + bb.z; o.w = hi2(acc[r][1]) + bb.w;
        *(float4*)(O + row * 256 + cc0) = o;
    }
}

// ---------------- dataflow recurrence: quad-interleaved W, 16B dot loads ----
// Wq layout: Wq[k4*128 + lane*4 + s] = W[4*k4+s][cb*32+lane]  (k4 = 0..63).
// One LDS.128 (ulonglong2) yields 4 k-values for this lane's column.
__global__ void __launch_bounds__(NTH) rec_kernel(
    const float* __restrict__ Wih, const float* __restrict__ Woh,
    const float* __restrict__ Wuh, const float* __restrict__ Wfh,
    const float* __restrict__ bih_g, const float* __restrict__ bfh_g)
{
    extern __shared__ __align__(16) float sm[];
    float* Wi = sm;
    float* Wo = sm + 8192;
    float* Wu = sm + 16384;
    float* Wf = sm + 24576;
    float* hchAll = sm + 32768;  // 16 warps x 256

    const int t = threadIdx.x;
    const int lane = t & 31, w = t >> 5;
    const int cb = blockIdx.x & 7;
    const int col = cb * 32 + lane;

    for (int idx = t; idx < 8192; idx += NTH) {
        int k4 = idx >> 7, r = idx & 127;
        int j = r >> 2, s = r & 3;
        int gidx = (4 * k4 + s) * 256 + cb * 32 + j;
        Wi[idx] = Wih[gidx];
        Wo[idx] = Woh[gidx];
        Wu[idx] = Wuh[gidx];
        Wf[idx] = Wfh[gidx];
    }
    const float bih = bih_g[col];
    const float bfh = bfh_g[col];
    float* hch = hchAll + w * 256;
    __syncthreads();

    // ---------------- leaf phase: no dependencies, quad grabs ----------------
    const int nleaf = g_nleaf;
    for (;;) {
        int pos;
        if (lane == 0) pos = atomicAdd(&g_curL[cb * 32], 4);
        pos = __shfl_sync(0xffffffffu, pos, 0);
        if (pos >= nleaf) break;
        int lim = (pos + 4 < nleaf) ? pos + 4 : nleaf;
        for (int p2 = pos; p2 < lim; p2++) {
            int n = g_level_nodes[p2];
            float ixv = __ldcg(g_ix + n * 256 + col);
            float oxv = __ldcg(g_ox + n * 256 + col);
            float uxv = __ldcg(g_ux + n * 256 + col);
            float iv = sigm(ixv + bih);
            float ov = sigm(oxv);
            float cn = iv * tanhf(uxv);
            __stcg(g_c + n * 256 + col, cn);
            __stcg(g_h + n * 256 + col, ov * tanhf(cn));
            __syncwarp();
            if (lane == 0) red_release(&g_done[n]);
        }
    }

    // ---------------- interior phase: pull with child prefetch --------------
    for (;;) {
        int pos;
        if (lane == 0) pos = atomicAdd(&g_curI[cb * 32], 1);
        pos = __shfl_sync(0xffffffffu, pos, 0);
        if (pos >= Nn) break;
        int n = g_level_nodes[pos];
        int cs0 = g_child_start[n], cs1 = g_child_start[n + 1];
        float ixv = g_ix[n * 256 + col];
        float oxv = g_ox[n * 256 + col];
        float uxv = g_ux[n * 256 + col];
        float fxn = g_fx[n * 256 + col];

        float rs[8];
#pragma unroll
        for (int q = 0; q < 8; q++) rs[q] = 0.f;
        float fc = 0.f;
        float hreg[8], cpre;

        // prologue: wait + load first child into registers
        {
            int ch = g_child_list[cs0];
            waitdone(&g_done[ch]);
            const float* hrow = g_h + ch * 256;
#pragma unroll
            for (int q = 0; q < 8; q++) hreg[q] = __ldcg(hrow + q * 32 + lane);
            cpre = __ldcg(g_c + ch * 256 + col);
        }

        for (int e = cs0; e < cs1; e++) {
            // commit current child to smem + running sum
#pragma unroll
            for (int q = 0; q < 8; q++) {
                hch[q * 32 + lane] = hreg[q];
                rs[q] += hreg[q];
            }
            float ccur = cpre;
            __syncwarp();
            // prefetch next child (loads overlap the f-dot below)
            if (e + 1 < cs1) {
                int ch = g_child_list[e + 1];
                waitdone(&g_done[ch]);
                const float* hrow = g_h + ch * 256;
#pragma unroll
                for (int q = 0; q < 8; q++) hreg[q] = __ldcg(hrow + q * 32 + lane);
                cpre = __ldcg(g_c + ch * 256 + col);
            }
            // f-dot over committed child: 4 k-values per 16B load
            u64 a0 = 0, a1 = 0, a2 = 0, a3 = 0;
#pragma unroll 8
            for (int k4 = 0; k4 < 64; k4 += 2) {
                ulonglong2 h0 = *(const ulonglong2*)(hch + 4 * k4);
                ulonglong2 w0 = *(const ulonglong2*)(Wf + k4 * 128 + lane * 4);
                fma2(a0, h0.x, w0.x); fma2(a1, h0.y, w0.y);
                ulonglong2 h1 = *(const ulonglong2*)(hch + 4 * k4 + 4);
                ulonglong2 w1 = *(const ulonglong2*)(Wf + (k4 + 1) * 128 + lane * 4);
                fma2(a2, h1.x, w1.x); fma2(a3, h1.y, w1.y);
            }
            float fd = red2(a0) + red2(a1) + red2(a2) + red2(a3);
            float f = sigm(fd + bfh + fxn);
            fc = fmaf(f, ccur, fc);
            __syncwarp();
        }

        // h_sum -> smem (broadcast source for i/o/u dots)
#pragma unroll
        for (int q = 0; q < 8; q++) hch[q * 32 + lane] = rs[q];
        __syncwarp();
        u64 i0 = 0, i1 = 0, o0 = 0, o1 = 0, u0 = 0, u1 = 0;
#pragma unroll 8
        for (int k4 = 0; k4 < 64; k4++) {
            ulonglong2 hh = *(const ulonglong2*)(hch + 4 * k4);
            ulonglong2 wi = *(const ulonglong2*)(Wi + k4 * 128 + lane * 4);
            ulonglong2 wo = *(const ulonglong2*)(Wo + k4 * 128 + lane * 4);
            ulonglong2 wu = *(const ulonglong2*)(Wu + k4 * 128 + lane * 4);
            fma2(i0, hh.x, wi.x); fma2(i1, hh.y, wi.y);
            fma2(o0, hh.x, wo.x); fma2(o1, hh.y, wo.y);
            fma2(u0, hh.x, wu.x); fma2(u1, hh.y, wu.y);
        }
        float iv = sigm(ixv + red2(i0) + red2(i1) + bih);
        float ov = sigm(oxv + red2(o0) + red2(o1));
        float uv = tanhf(uxv + red2(u0) + red2(u1));
        float cn = fmaf(iv, uv, fc);
        __syncwarp();

        __stcg(g_c + n * 256 + col, cn);
        __stcg(g_h + n * 256 + col, ov * tanhf(cn));
        __syncwarp();
        if (lane == 0) red_release(&g_done[n]);
    }
}

// ---------------- parallel 2-stage max-pool + output ------------------------
__global__ void __launch_bounds__(256) pool1_kernel()
{
    int b = blockIdx.x, chn = blockIdx.y, t = threadIdx.x;
    const float* hb = g_h + ((size_t)b * St + chn * 16) * Hh;
    float m = -1e30f;
#pragma unroll
    for (int s2 = 0; s2 < 16; s2++) m = fmaxf(m, hb[s2 * Hh + t]);
    g_pool[(b * 8 + chn) * Hh + t] = m;
}

__global__ void __launch_bounds__(256) pool2_kernel(
    const float* __restrict__ Wout, const float* __restrict__ bout,
    float* __restrict__ out)
{
    __shared__ float pooled[Hh];
    int b = blockIdx.x, t = threadIdx.x;
    float m = -1e30f;
#pragma unroll
    for (int chn = 0; chn < 8; chn++)
        m = fmaxf(m, g_pool[(b * 8 + chn) * Hh + t]);
    pooled[t] = m;
    __syncthreads();
    if (t < Lc) {
        float acc = bout[t];
        for (int k = 0; k < Hh; k++) acc = fmaf(pooled[k], Wout[k * Lc + t], acc);
        out[b * Lc + t] = acc;
    }
}

// ---------------- host-side launch ------------------------------------------
extern "C" void kernel_launch(void* const* d_in, const int* in_sizes, int n_in,
                              void* d_out, int out_size)
{
    int off = (in_sizes[5] == 1) ? 6 : 5;

    const int* xs        = (const int*)d_in[0];
    const int* rels      = (const int*)d_in[1];
    const int* child_idx = (const int*)d_in[2];
    const int* parent_idx= (const int*)d_in[3];
    const int* height    = (const int*)d_in[4];
    const float* embW  = (const float*)d_in[off + 0];
    const float* relW  = (const float*)d_in[off + 1];
    const float* W_ix  = (const float*)d_in[off + 2];
    const float* b_ix  = (const float*)d_in[off + 3];
    const float* W_ih  = (const float*)d_in[off + 4];
    const float* b_ih  = (const float*)d_in[off + 5];
    const float* W_fx  = (const float*)d_in[off + 6];
    const float* b_fx  = (const float*)d_in[off + 7];
    const float* W_fh  = (const float*)d_in[off + 8];
    const float* b_fh  = (const float*)d_in[off + 9];
    const float* W_ox  = (const float*)d_in[off + 10];
    const float* W_oh  = (const float*)d_in[off + 11];
    const float* W_ux  = (const float*)d_in[off + 12];
    const float* W_uh  = (const float*)d_in[off + 13];
    const float* W_out = (const float*)d_in[off + 14];
    const float* b_out = (const float*)d_in[off + 15];

    cudaFuncSetAttribute(rec_kernel,
                         cudaFuncAttributeMaxDynamicSharedMemorySize, 147456);

    preprocess_kernel<<<1, 512>>>(child_idx, parent_idx, height);
    dim3 gg(4, 32, 4);
    input_gemm_kernel<<<gg, 256>>>(xs, rels, embW, relW,
                                   W_ix, W_fx, W_ox, W_ux, b_ix, b_fx);
    rec_kernel<<<NCTA, NTH, 147456>>>(W_ih, W_oh, W_uh, W_fh, b_ih, b_fh);
    pool1_kernel<<<dim3(16, 8), 256>>>();
    pool2_kernel<<<Bt, 256>>>(W_out, b_out, (float*)d_out);
}